// round 6
// baseline (speedup 1.0000x reference)
#include <cuda_runtime.h>
#include <cuda_pipeline.h>
#include <math.h>
#include <stdint.h>

// ---------------- problem constants ----------------
#define T_STEPS 1000
#define BATCH   64
#define IN_DIM  512
#define HID     1024
#define OUT_DIM 64
#define NY      65            // O + 1 (policy + value)
#define E_SZ    819           // excitatory / nonzero readout columns
#define ALPHA   0.2f
#define OMALPHA 0.8f

// ---------------- phase-2 config ----------------
#define NCTA 128              // persistent CTAs (single wave on 148 SMs)
#define HSL  8                // H columns per CTA (NCTA*HSL == HID)
#define OPAD 80               // padded readout width (float4-friendly)

// ---------------- device scratch (no allocations allowed) ----------------
__device__ float g_xq[(size_t)T_STEPS * HID * BATCH];     // [t][h][b] input projection
__device__ float g_outAll[(size_t)T_STEPS * HID * BATCH]; // [t][j][b] activation history
__device__ float g_eWhP[NCTA * HID * HSL];                // [cta][j][hl] packed recurrent weights
__device__ float g_eWoT[HID * OPAD];                      // [j][o] readout weights (o=64 is value head)
__device__ unsigned g_count;                              // barrier arrivals
__device__ volatile unsigned g_flag;                      // barrier sense (even flips/launch -> replay safe)

// ---------------- f32x2 packed math ----------------
__device__ __forceinline__ unsigned long long pk2(float x, float y) {
    unsigned long long r;
    asm("mov.b64 %0, {%1, %2};" : "=l"(r) : "r"(__float_as_uint(x)), "r"(__float_as_uint(y)));
    return r;
}
__device__ __forceinline__ void upk2(unsigned long long v, float &x, float &y) {
    unsigned xi, yi;
    asm("mov.b64 {%0, %1}, %2;" : "=r"(xi), "=r"(yi) : "l"(v));
    x = __uint_as_float(xi); y = __uint_as_float(yi);
}
__device__ __forceinline__ unsigned long long ffma2(unsigned long long a,
                                                    unsigned long long b,
                                                    unsigned long long c) {
    unsigned long long d;
    asm("fma.rn.f32x2 %0, %1, %2, %3;" : "=l"(d) : "l"(a), "l"(b), "l"(c));
    return d;
}

// ---------------- prep: masked effective weights ----------------
__global__ void prep_kernel(const float* __restrict__ Wh,
                            const float* __restrict__ Wo,
                            const float* __restrict__ Wv) {
    int idx = blockIdx.x * blockDim.x + threadIdx.x;
    const int N1 = HID * HID;
    if (idx < N1) {
        int h = idx >> 10, j = idx & 1023;
        float v = Wh[idx];
        v = v > 0.f ? v : 0.f;                 // relu(W)
        float s = (j < E_SZ) ? 1.f : -1.f;     // Dale sign by presynaptic column
        v = (h == j) ? 0.f : v * s;            // zero diagonal
        g_eWhP[(size_t)(h >> 3) * (HID * HSL) + (size_t)j * HSL + (h & 7)] = v;
    } else if (idx < N1 + NY * HID) {
        int i2 = idx - N1;
        int o = i2 >> 10, j = i2 & 1023;
        float v = (o < OUT_DIM) ? Wo[o * HID + j] : Wv[j];
        v = v > 0.f ? v : 0.f;
        if (j >= E_SZ) v = 0.f;                // masked readout columns
        g_eWoT[(size_t)j * OPAD + o] = v;
    }
}

// ---------------- phase 1: g_xq[t][h][b] = sum_k x[t][b][k]*relu(Wx[h][k]) ----------------
// Tile 64b x 128h, K-tile 16, 256 threads, per-thread 4b x 8h via f32x2.
__global__ __launch_bounds__(256) void xproj_kernel(const float* __restrict__ x,
                                                    const float* __restrict__ Wx) {
    __shared__ float As[16][64];    // [k][b]
    __shared__ float Bs[16][128];   // [k][h]
    const int t  = blockIdx.y;
    const int h0 = blockIdx.x * 128;
    const int tid = threadIdx.x;
    const int tx = tid & 15;        // b-group (4 b)
    const int ty = tid >> 4;        // h-group (8 h = 4 pairs)

    unsigned long long acc[4][4];
#pragma unroll
    for (int i = 0; i < 4; i++)
#pragma unroll
        for (int p = 0; p < 4; p++) acc[i][p] = 0ull;

    const float* xb = x + (size_t)t * BATCH * IN_DIM;
    const int bb  = tid >> 2;             // 0..63
    const int kk4 = (tid & 3) << 2;       // 0,4,8,12
    const int hh  = tid & 127;            // 0..127
    const int kq  = (tid >> 7) << 3;      // 0 or 8

    for (int k0 = 0; k0 < IN_DIM; k0 += 16) {
        __syncthreads();
        float4 av = *(const float4*)&xb[(size_t)bb * IN_DIM + k0 + kk4];
        As[kk4 + 0][bb] = av.x; As[kk4 + 1][bb] = av.y;
        As[kk4 + 2][bb] = av.z; As[kk4 + 3][bb] = av.w;
        const float* wrow = Wx + (size_t)(h0 + hh) * IN_DIM + k0 + kq;
        float4 w0 = *(const float4*)wrow;
        float4 w1 = *(const float4*)(wrow + 4);
        Bs[kq + 0][hh] = fmaxf(w0.x, 0.f); Bs[kq + 1][hh] = fmaxf(w0.y, 0.f);
        Bs[kq + 2][hh] = fmaxf(w0.z, 0.f); Bs[kq + 3][hh] = fmaxf(w0.w, 0.f);
        Bs[kq + 4][hh] = fmaxf(w1.x, 0.f); Bs[kq + 5][hh] = fmaxf(w1.y, 0.f);
        Bs[kq + 6][hh] = fmaxf(w1.z, 0.f); Bs[kq + 7][hh] = fmaxf(w1.w, 0.f);
        __syncthreads();
#pragma unroll
        for (int kk = 0; kk < 16; kk++) {
            float4 a = *(const float4*)&As[kk][tx << 2];
            ulonglong2 wA = *(const ulonglong2*)&Bs[kk][(ty << 3)];
            ulonglong2 wB = *(const ulonglong2*)&Bs[kk][(ty << 3) + 4];
            unsigned long long a0 = pk2(a.x, a.x), a1 = pk2(a.y, a.y);
            unsigned long long a2 = pk2(a.z, a.z), a3 = pk2(a.w, a.w);
            acc[0][0] = ffma2(a0, wA.x, acc[0][0]); acc[0][1] = ffma2(a0, wA.y, acc[0][1]);
            acc[0][2] = ffma2(a0, wB.x, acc[0][2]); acc[0][3] = ffma2(a0, wB.y, acc[0][3]);
            acc[1][0] = ffma2(a1, wA.x, acc[1][0]); acc[1][1] = ffma2(a1, wA.y, acc[1][1]);
            acc[1][2] = ffma2(a1, wB.x, acc[1][2]); acc[1][3] = ffma2(a1, wB.y, acc[1][3]);
            acc[2][0] = ffma2(a2, wA.x, acc[2][0]); acc[2][1] = ffma2(a2, wA.y, acc[2][1]);
            acc[2][2] = ffma2(a2, wB.x, acc[2][2]); acc[2][3] = ffma2(a2, wB.y, acc[2][3]);
            acc[3][0] = ffma2(a3, wA.x, acc[3][0]); acc[3][1] = ffma2(a3, wA.y, acc[3][1]);
            acc[3][2] = ffma2(a3, wB.x, acc[3][2]); acc[3][3] = ffma2(a3, wB.y, acc[3][3]);
        }
    }
    float* xqo = g_xq + (size_t)t * (HID * BATCH);
#pragma unroll
    for (int i = 0; i < 4; i++) {
        int b = (tx << 2) + i;
#pragma unroll
        for (int p = 0; p < 4; p++) {
            float f0, f1; upk2(acc[i][p], f0, f1);
            int h = h0 + (ty << 3) + (p << 1);
            xqo[(size_t)h * 64 + b]       = f0;
            xqo[(size_t)(h + 1) * 64 + b] = f1;
        }
    }
}

// ---------------- grid barrier (sense reversing) ----------------
__device__ __forceinline__ void grid_barrier(unsigned &sense) {
    sense ^= 1u;
    __threadfence();                 // publish this thread's global writes
    __syncthreads();
    if (threadIdx.x == 0) {
        unsigned old = atomicAdd(&g_count, 1u);
        if (old == NCTA - 1) {
            g_count = 0;
            __threadfence();
            g_flag = sense;          // release
        } else {
            while (g_flag != sense) { }
            __threadfence();         // acquire
        }
    }
    __syncthreads();
}

// ---------------- phase 2: persistent recurrent kernel ----------------
// 128 CTAs x 256 threads. CTA owns 8 H-cols (weights resident in shared for the
// whole launch). Thread: b = tid&63, jg = tid>>6 (j-reduction split 4 ways),
// accumulates all 8 h via 4 f32x2 pairs; cross-jg reduce through shared.
// Activation broadcast staged via 4-stage cp.async ring (64 j x 64 b tiles).
extern __shared__ float rnn_smem[];
__global__ __launch_bounds__(256, 1) void rnn_kernel(const float* __restrict__ bh) {
    float* sW   = rnn_smem;          // 8192 floats (32 KB) - resident weights
    float* sOut = rnn_smem + 8192;   // 4 x 4096 floats ring (64 KB)
    unsigned long long* sRedq = (unsigned long long*)sOut; // reduction scratch (reuses ring)

    const int cta = blockIdx.x;
    const int tid = threadIdx.x;
    const int b   = tid & 63;
    const int jg  = tid >> 6;
    const int h0  = cta * HSL;
    const int hA  = h0 + jg * 2;

    // load this CTA's weights into shared ONCE (used for all 1000 steps)
    {
        const float4* wsrc = (const float4*)(g_eWhP + (size_t)cta * (HID * HSL));
        float4* wdst = (float4*)sW;
#pragma unroll
        for (int k = 0; k < 8; k++) wdst[tid + k * 256] = wsrc[tid + k * 256];
    }

    const float bh0 = bh[hA], bh1 = bh[hA + 1];
    float st0, st1;
    unsigned sense = 0;

    // ---- step 0: out_prev == 0 -> total = xproj + bias only ----
    {
        float xq0 = g_xq[(size_t)hA * 64 + b];
        float xq1 = g_xq[(size_t)(hA + 1) * 64 + b];
        st0 = ALPHA * (xq0 + bh0);
        st1 = ALPHA * (xq1 + bh1);
        g_outAll[(size_t)hA * 64 + b]       = tanhf(fmaxf(st0, 0.f));
        g_outAll[(size_t)(hA + 1) * 64 + b] = tanhf(fmaxf(st1, 0.f));
    }
    grid_barrier(sense);   // barrier #1 (also orders the sW staging for all threads)

    // ---- steps 1..999 ----
    for (int t = 1; t < T_STEPS; t++) {
        const float* outPrev = g_outAll + (size_t)(t - 1) * (HID * BATCH);
        float xq0 = g_xq[(size_t)t * (HID * BATCH) + (size_t)hA * 64 + b];
        float xq1 = g_xq[(size_t)t * (HID * BATCH) + (size_t)(hA + 1) * 64 + b];

        // prologue: prefetch tiles 0..2
#pragma unroll
        for (int pti = 0; pti < 3; pti++) {
#pragma unroll
            for (int k = 0; k < 4; k++) {
                int fid = tid + k * 256;
                __pipeline_memcpy_async((float4*)(sOut + pti * 4096) + fid,
                                        (const float4*)(outPrev + (size_t)pti * 4096) + fid, 16);
            }
            __pipeline_commit();
        }

        unsigned long long acc0 = 0, acc1 = 0, acc2 = 0, acc3 = 0;
        for (int ti = 0; ti < 16; ti++) {
            __pipeline_wait_prior(2);   // tile ti's group complete (per thread)
            __syncthreads();            // -> whole tile complete
            if (ti + 3 < 16) {
                int nt = ti + 3;
#pragma unroll
                for (int k = 0; k < 4; k++) {
                    int fid = tid + k * 256;
                    __pipeline_memcpy_async((float4*)(sOut + (nt & 3) * 4096) + fid,
                                            (const float4*)(outPrev + (size_t)nt * 4096) + fid, 16);
                }
            }
            __pipeline_commit();        // commit even when empty: keeps group accounting fixed
            const float* buf = sOut + (ti & 3) * 4096;
#pragma unroll
            for (int i = 0; i < 16; i++) {
                int lj = jg * 16 + i;   // this jg's 16 j's within the 64-j tile
                float ov = buf[lj * 64 + b];
                unsigned long long a = pk2(ov, ov);
                const ulonglong2* wq = (const ulonglong2*)(sW + (size_t)(ti * 64 + lj) * 8);
                ulonglong2 wA = wq[0], wB = wq[1];
                acc0 = ffma2(a, wA.x, acc0);
                acc1 = ffma2(a, wA.y, acc1);
                acc2 = ffma2(a, wB.x, acc2);
                acc3 = ffma2(a, wB.y, acc3);
            }
        }

        // cross-jg reduction (pairs: p covers h0+2p, h0+2p+1; thread owns pair jg)
        __syncthreads();
        sRedq[((size_t)jg * 64 + b) * 4 + 0] = acc0;
        sRedq[((size_t)jg * 64 + b) * 4 + 1] = acc1;
        sRedq[((size_t)jg * 64 + b) * 4 + 2] = acc2;
        sRedq[((size_t)jg * 64 + b) * 4 + 3] = acc3;
        __syncthreads();
        float r0 = 0.f, r1 = 0.f;
#pragma unroll
        for (int g = 0; g < 4; g++) {
            float f0, f1;
            upk2(sRedq[((size_t)g * 64 + b) * 4 + jg], f0, f1);
            r0 += f0; r1 += f1;
        }

        st0 = OMALPHA * st0 + ALPHA * (xq0 + r0 + bh0);
        st1 = OMALPHA * st1 + ALPHA * (xq1 + r1 + bh1);
        float* outCur = g_outAll + (size_t)t * (HID * BATCH);
        outCur[(size_t)hA * 64 + b]       = tanhf(fmaxf(st0, 0.f));
        outCur[(size_t)(hA + 1) * 64 + b] = tanhf(fmaxf(st1, 0.f));

        grid_barrier(sense);   // barriers #2..#1000 -> 1000 total (even): flag returns to 0
    }
}

// ---------------- phase 3: readout over stored history ----------------
// One block per t. y[t][b][o] = sum_j out[t][j][b] * eWoT[j][o] + bias.
__global__ __launch_bounds__(256) void readout_kernel(const float* __restrict__ bo,
                                                      const float* __restrict__ bv,
                                                      float* __restrict__ y) {
    __shared__ float outS[64][64];
    const int t = blockIdx.x;
    const int tid = threadIdx.x;
    const int tx = tid & 15, ty = tid >> 4;
    const int b4 = tx * 4, o4 = ty * 4;
    const float* outT = g_outAll + (size_t)t * (HID * BATCH);

    float acc[4][4];
#pragma unroll
    for (int i = 0; i < 4; i++)
#pragma unroll
        for (int p = 0; p < 4; p++) acc[i][p] = 0.f;
    float accv[4] = {0.f, 0.f, 0.f, 0.f};

    for (int tile = 0; tile < 16; tile++) {
        __syncthreads();
#pragma unroll
        for (int k = 0; k < 4; k++) {
            int fid = tid + k * 256;
            ((float4*)&outS[0][0])[fid] = ((const float4*)(outT + (size_t)tile * 4096))[fid];
        }
        __syncthreads();
#pragma unroll 4
        for (int jj = 0; jj < 64; jj++) {
            int j = tile * 64 + jj;
            float4 ov = *(const float4*)&outS[jj][b4];
            float4 wv = __ldg((const float4*)(g_eWoT + (size_t)j * OPAD) + ty);
            acc[0][0] += ov.x * wv.x; acc[0][1] += ov.x * wv.y;
            acc[0][2] += ov.x * wv.z; acc[0][3] += ov.x * wv.w;
            acc[1][0] += ov.y * wv.x; acc[1][1] += ov.y * wv.y;
            acc[1][2] += ov.y * wv.z; acc[1][3] += ov.y * wv.w;
            acc[2][0] += ov.z * wv.x; acc[2][1] += ov.z * wv.y;
            acc[2][2] += ov.z * wv.z; acc[2][3] += ov.z * wv.w;
            acc[3][0] += ov.w * wv.x; acc[3][1] += ov.w * wv.y;
            acc[3][2] += ov.w * wv.z; acc[3][3] += ov.w * wv.w;
            if (ty == 0) {
                float w64 = __ldg(g_eWoT + (size_t)j * OPAD + 64);
                accv[0] += ov.x * w64; accv[1] += ov.y * w64;
                accv[2] += ov.z * w64; accv[3] += ov.w * w64;
            }
        }
    }

    float* yt = y + (size_t)t * (BATCH * NY);
#pragma unroll
    for (int i = 0; i < 4; i++) {
#pragma unroll
        for (int p = 0; p < 4; p++)
            yt[(size_t)(b4 + i) * NY + (o4 + p)] = acc[i][p] + bo[o4 + p];
        if (ty == 0)
            yt[(size_t)(b4 + i) * NY + 64] = accv[i] + bv[0];
    }
}

// ---------------- launcher ----------------
extern "C" void kernel_launch(void* const* d_in, const int* in_sizes, int n_in,
                              void* d_out, int out_size) {
    const float* x  = (const float*)d_in[0];
    const float* Wx = (const float*)d_in[1];
    const float* Wh = (const float*)d_in[2];
    const float* bh = (const float*)d_in[3];
    const float* Wo = (const float*)d_in[4];
    const float* bo = (const float*)d_in[5];
    const float* Wv = (const float*)d_in[6];
    const float* bv = (const float*)d_in[7];
    float* y = (float*)d_out;
    (void)in_sizes; (void)n_in; (void)out_size;

    // masked effective weights
    {
        int total = HID * HID + NY * HID;
        prep_kernel<<<(total + 255) / 256, 256>>>(Wh, Wo, Wv);
    }
    // input projection for all timesteps (no sequential dependency)
    xproj_kernel<<<dim3(HID / 128, T_STEPS), 256>>>(x, Wx);
    // persistent recurrence: 32KB weights + 64KB cp.async ring = 96KB dynamic smem
    static const int RNN_SMEM = 96 * 1024;
    cudaFuncSetAttribute(rnn_kernel, cudaFuncAttributeMaxDynamicSharedMemorySize, RNN_SMEM);
    rnn_kernel<<<NCTA, 256, RNN_SMEM>>>(bh);
    // readout for all timesteps
    readout_kernel<<<T_STEPS, 256>>>(bo, bv, y);
}

// round 7
// speedup vs baseline: 1.2020x; 1.2020x over previous
#include <cuda_runtime.h>
#include <cuda_pipeline.h>
#include <math.h>
#include <stdint.h>

// ---------------- problem constants ----------------
#define T_STEPS 1000
#define BATCH   64
#define IN_DIM  512
#define HID     1024
#define OUT_DIM 64
#define NY      65            // O + 1 (policy + value)
#define E_SZ    819           // excitatory / nonzero readout columns
#define ALPHA   0.2f
#define OMALPHA 0.8f

// ---------------- phase-2 config ----------------
// 128 CTAs = 32 h-groups (32 h each) x 4 batch-quarters (16 b each).
#define NCTA 128
#define HPC  32               // h per CTA
#define BPC  16               // b per CTA
#define OPAD 80               // padded readout width (float4-friendly)

// ---------------- device scratch (no allocations allowed) ----------------
__device__ float g_xq[(size_t)T_STEPS * HID * BATCH];     // [t][h][b] input projection
__device__ float g_outAll[(size_t)T_STEPS * HID * BATCH]; // [t][j][b] activation history
__device__ float g_eWhP[32 * 1024 * 32];                  // [hgrp][j][hl] packed recurrent weights
__device__ float g_eWoT[HID * OPAD];                      // [j][o] readout weights (o=64 -> value head)
__device__ unsigned g_count;                              // barrier arrivals
__device__ volatile unsigned g_flag;                      // barrier sense (1000 flips/launch... even -> replay safe)

// ---------------- f32x2 packed math ----------------
__device__ __forceinline__ unsigned long long pk2(float x, float y) {
    unsigned long long r;
    asm("mov.b64 %0, {%1, %2};" : "=l"(r) : "r"(__float_as_uint(x)), "r"(__float_as_uint(y)));
    return r;
}
__device__ __forceinline__ void upk2(unsigned long long v, float &x, float &y) {
    unsigned xi, yi;
    asm("mov.b64 {%0, %1}, %2;" : "=r"(xi), "=r"(yi) : "l"(v));
    x = __uint_as_float(xi); y = __uint_as_float(yi);
}
__device__ __forceinline__ unsigned long long ffma2(unsigned long long a,
                                                    unsigned long long b,
                                                    unsigned long long c) {
    unsigned long long d;
    asm("fma.rn.f32x2 %0, %1, %2, %3;" : "=l"(d) : "l"(a), "l"(b), "l"(c));
    return d;
}

// ---------------- prep: masked effective weights ----------------
__global__ void prep_kernel(const float* __restrict__ Wh,
                            const float* __restrict__ Wo,
                            const float* __restrict__ Wv) {
    int idx = blockIdx.x * blockDim.x + threadIdx.x;
    const int N1 = HID * HID;
    if (idx < N1) {
        int h = idx >> 10, j = idx & 1023;
        float v = Wh[idx];
        v = v > 0.f ? v : 0.f;                 // relu(W)
        float s = (j < E_SZ) ? 1.f : -1.f;     // Dale sign by presynaptic column
        v = (h == j) ? 0.f : v * s;            // zero diagonal
        // pack by h-group: [hgrp][j][h&31]
        g_eWhP[(size_t)(h >> 5) * 32768 + (size_t)j * 32 + (h & 31)] = v;
    } else if (idx < N1 + NY * HID) {
        int i2 = idx - N1;
        int o = i2 >> 10, j = i2 & 1023;
        float v = (o < OUT_DIM) ? Wo[o * HID + j] : Wv[j];
        v = v > 0.f ? v : 0.f;
        if (j >= E_SZ) v = 0.f;                // masked readout columns
        g_eWoT[(size_t)j * OPAD + o] = v;
    }
}

// ---------------- phase 1: g_xq[t][h][b] = sum_k x[t][b][k]*relu(Wx[h][k]) ----------------
// Tile 64b x 128h, K-tile 16, 256 threads, per-thread 4b x 8h via f32x2.
__global__ __launch_bounds__(256) void xproj_kernel(const float* __restrict__ x,
                                                    const float* __restrict__ Wx) {
    __shared__ float As[16][64];    // [k][b]
    __shared__ float Bs[16][128];   // [k][h]
    const int t  = blockIdx.y;
    const int h0 = blockIdx.x * 128;
    const int tid = threadIdx.x;
    const int tx = tid & 15;        // b-group (4 b)
    const int ty = tid >> 4;        // h-group (8 h = 4 pairs)

    unsigned long long acc[4][4];
#pragma unroll
    for (int i = 0; i < 4; i++)
#pragma unroll
        for (int p = 0; p < 4; p++) acc[i][p] = 0ull;

    const float* xb = x + (size_t)t * BATCH * IN_DIM;
    const int bb  = tid >> 2;             // 0..63
    const int kk4 = (tid & 3) << 2;       // 0,4,8,12
    const int hh  = tid & 127;            // 0..127
    const int kq  = (tid >> 7) << 3;      // 0 or 8

    for (int k0 = 0; k0 < IN_DIM; k0 += 16) {
        __syncthreads();
        float4 av = *(const float4*)&xb[(size_t)bb * IN_DIM + k0 + kk4];
        As[kk4 + 0][bb] = av.x; As[kk4 + 1][bb] = av.y;
        As[kk4 + 2][bb] = av.z; As[kk4 + 3][bb] = av.w;
        const float* wrow = Wx + (size_t)(h0 + hh) * IN_DIM + k0 + kq;
        float4 w0 = *(const float4*)wrow;
        float4 w1 = *(const float4*)(wrow + 4);
        Bs[kq + 0][hh] = fmaxf(w0.x, 0.f); Bs[kq + 1][hh] = fmaxf(w0.y, 0.f);
        Bs[kq + 2][hh] = fmaxf(w0.z, 0.f); Bs[kq + 3][hh] = fmaxf(w0.w, 0.f);
        Bs[kq + 4][hh] = fmaxf(w1.x, 0.f); Bs[kq + 5][hh] = fmaxf(w1.y, 0.f);
        Bs[kq + 6][hh] = fmaxf(w1.z, 0.f); Bs[kq + 7][hh] = fmaxf(w1.w, 0.f);
        __syncthreads();
#pragma unroll
        for (int kk = 0; kk < 16; kk++) {
            float4 a = *(const float4*)&As[kk][tx << 2];
            ulonglong2 wA = *(const ulonglong2*)&Bs[kk][(ty << 3)];
            ulonglong2 wB = *(const ulonglong2*)&Bs[kk][(ty << 3) + 4];
            unsigned long long a0 = pk2(a.x, a.x), a1 = pk2(a.y, a.y);
            unsigned long long a2 = pk2(a.z, a.z), a3 = pk2(a.w, a.w);
            acc[0][0] = ffma2(a0, wA.x, acc[0][0]); acc[0][1] = ffma2(a0, wA.y, acc[0][1]);
            acc[0][2] = ffma2(a0, wB.x, acc[0][2]); acc[0][3] = ffma2(a0, wB.y, acc[0][3]);
            acc[1][0] = ffma2(a1, wA.x, acc[1][0]); acc[1][1] = ffma2(a1, wA.y, acc[1][1]);
            acc[1][2] = ffma2(a1, wB.x, acc[1][2]); acc[1][3] = ffma2(a1, wB.y, acc[1][3]);
            acc[2][0] = ffma2(a2, wA.x, acc[2][0]); acc[2][1] = ffma2(a2, wA.y, acc[2][1]);
            acc[2][2] = ffma2(a2, wB.x, acc[2][2]); acc[2][3] = ffma2(a2, wB.y, acc[2][3]);
            acc[3][0] = ffma2(a3, wA.x, acc[3][0]); acc[3][1] = ffma2(a3, wA.y, acc[3][1]);
            acc[3][2] = ffma2(a3, wB.x, acc[3][2]); acc[3][3] = ffma2(a3, wB.y, acc[3][3]);
        }
    }
    float* xqo = g_xq + (size_t)t * (HID * BATCH);
#pragma unroll
    for (int i = 0; i < 4; i++) {
        int b = (tx << 2) + i;
#pragma unroll
        for (int p = 0; p < 4; p++) {
            float f0, f1; upk2(acc[i][p], f0, f1);
            int h = h0 + (ty << 3) + (p << 1);
            xqo[(size_t)h * 64 + b]       = f0;
            xqo[(size_t)(h + 1) * 64 + b] = f1;
        }
    }
}

// ---------------- grid barrier (sense reversing) ----------------
__device__ __forceinline__ void grid_barrier(unsigned &sense) {
    sense ^= 1u;
    __threadfence();                 // publish this thread's global writes
    __syncthreads();
    if (threadIdx.x == 0) {
        unsigned old = atomicAdd(&g_count, 1u);
        if (old == NCTA - 1) {
            g_count = 0;
            __threadfence();
            g_flag = sense;          // release
        } else {
            while (g_flag != sense) { }
            __threadfence();         // acquire
        }
    }
    __syncthreads();
}

// ---------------- phase 2: persistent recurrent kernel ----------------
// 128 CTAs x 256 threads. CTA = (hgrp, bq): 32 h-cols x 16 b. Weights (128 KB)
// resident in shared for all 1000 steps. Warp layout: lane = bq(4) x ho(8),
// warp id = jg (8-way j-split) -> conflict-free LDS, 8 ffma2 per 2 LDS.128.
// Activation quarter-slice (64 KB/step) staged via 4-stage cp.async ring.
extern __shared__ float rnn_smem[];
__global__ __launch_bounds__(256, 1) void rnn_kernel(const float* __restrict__ bh) {
    float* sW   = rnn_smem;                         // 32768 floats (128 KB) weights [j][32h]
    float* sOut = rnn_smem + 32768;                 // 4 x 1024 floats ring (16 KB)
    unsigned long long* sRed =
        (unsigned long long*)(rnn_smem + 32768 + 4096); // 8 x 257 ull reduction scratch

    const int cta  = blockIdx.x;
    const int tid  = threadIdx.x;
    const int hgrp = cta >> 2;
    const int b0   = (cta & 3) * BPC;
    const int lane = tid & 31;
    const int bq   = lane & 3;        // 4 b's: b = b0 + bq*4 + bi
    const int ho   = lane >> 2;       // 0..7: 4 h's: h = ho*4 + {0..3}
    const int jg   = tid >> 5;        // warp id = j-group (8-way)
    const int bql  = bq * 4;
    // output-ownership mapping (one h-pair x one b per thread)
    const int hpO  = tid >> 4;        // 0..15
    const int blO  = tid & 15;
    const int hOut = hgrp * 32 + hpO * 2;
    const int bOut = b0 + blO;
    // cp.async mapping (one 16B chunk per thread per tile)
    const int cpj = tid >> 2;         // 0..63 (j within tile)
    const int cpc = (tid & 3) * 4;    // 0,4,8,12 (b chunk)

    // load this CTA's weights into shared ONCE (used for all 1000 steps)
    {
        const float4* src = (const float4*)(g_eWhP + (size_t)hgrp * 32768);
        float4* dst = (float4*)sW;
#pragma unroll
        for (int k = 0; k < 32; k++) dst[tid + k * 256] = src[tid + k * 256];
    }

    const float bh0 = bh[hOut], bh1 = bh[hOut + 1];
    float st0, st1;
    unsigned sense = 0;

    // ---- step 0: out_prev == 0 -> total = xproj + bias only ----
    {
        float xq0 = g_xq[(size_t)hOut * 64 + bOut];
        float xq1 = g_xq[(size_t)(hOut + 1) * 64 + bOut];
        st0 = ALPHA * (xq0 + bh0);
        st1 = ALPHA * (xq1 + bh1);
        g_outAll[(size_t)hOut * 64 + bOut]       = tanhf(fmaxf(st0, 0.f));
        g_outAll[(size_t)(hOut + 1) * 64 + bOut] = tanhf(fmaxf(st1, 0.f));
    }
    grid_barrier(sense);   // barrier #1 (also orders sW staging for all threads)

    // ---- steps 1..999 ----
    for (int t = 1; t < T_STEPS; t++) {
        const float* outPrev = g_outAll + (size_t)(t - 1) * (HID * BATCH);
        const float* xqt = g_xq + (size_t)t * (HID * BATCH);
        float xq0 = xqt[(size_t)hOut * 64 + bOut];
        float xq1 = xqt[(size_t)(hOut + 1) * 64 + bOut];

        // prologue: prefetch tiles 0..2 (each tile = 64 j x 16 b = 4 KB)
#pragma unroll
        for (int pti = 0; pti < 3; pti++) {
            __pipeline_memcpy_async(sOut + pti * 1024 + cpj * 16 + cpc,
                                    outPrev + (size_t)(pti * 64 + cpj) * 64 + b0 + cpc, 16);
            __pipeline_commit();
        }

        unsigned long long acc[4][2];
#pragma unroll
        for (int i = 0; i < 4; i++) { acc[i][0] = 0ull; acc[i][1] = 0ull; }

        for (int ti = 0; ti < 16; ti++) {
            __pipeline_wait_prior(2);   // this thread's chunk of tile ti arrived
            __syncthreads();            // -> whole tile arrived, prior stage consumed
            if (ti < 13) {
                int nt = ti + 3;
                __pipeline_memcpy_async(sOut + (nt & 3) * 1024 + cpj * 16 + cpc,
                                        outPrev + (size_t)(nt * 64 + cpj) * 64 + b0 + cpc, 16);
            }
            __pipeline_commit();        // commit even when empty: fixed group accounting
            const float* buf = sOut + (ti & 3) * 1024;
            const float* wb  = sW + ti * 64 * 32 + ho * 4;
#pragma unroll
            for (int i = 0; i < 8; i++) {
                int lj = jg * 8 + i;
                float4 ov = *(const float4*)(buf + lj * 16 + bql);
                ulonglong2 w = *(const ulonglong2*)(wb + lj * 32);
                unsigned long long a0 = pk2(ov.x, ov.x);
                unsigned long long a1 = pk2(ov.y, ov.y);
                unsigned long long a2 = pk2(ov.z, ov.z);
                unsigned long long a3 = pk2(ov.w, ov.w);
                acc[0][0] = ffma2(a0, w.x, acc[0][0]); acc[0][1] = ffma2(a0, w.y, acc[0][1]);
                acc[1][0] = ffma2(a1, w.x, acc[1][0]); acc[1][1] = ffma2(a1, w.y, acc[1][1]);
                acc[2][0] = ffma2(a2, w.x, acc[2][0]); acc[2][1] = ffma2(a2, w.y, acc[2][1]);
                acc[3][0] = ffma2(a3, w.x, acc[3][0]); acc[3][1] = ffma2(a3, w.y, acc[3][1]);
            }
        }

        // cross-jg reduction: 8 partials per output (h-pair, b)
#pragma unroll
        for (int bi = 0; bi < 4; bi++)
#pragma unroll
            for (int hp = 0; hp < 2; hp++)
                sRed[jg * 257 + (ho * 2 + hp) * 16 + (bql + bi)] = acc[bi][hp];
        __syncthreads();
        float r0 = 0.f, r1 = 0.f;
#pragma unroll
        for (int g = 0; g < 8; g++) {
            float f0, f1;
            upk2(sRed[g * 257 + hpO * 16 + blO], f0, f1);
            r0 += f0; r1 += f1;
        }

        st0 = OMALPHA * st0 + ALPHA * (xq0 + r0 + bh0);
        st1 = OMALPHA * st1 + ALPHA * (xq1 + r1 + bh1);
        float* outCur = g_outAll + (size_t)t * (HID * BATCH);
        outCur[(size_t)hOut * 64 + bOut]       = tanhf(fmaxf(st0, 0.f));
        outCur[(size_t)(hOut + 1) * 64 + bOut] = tanhf(fmaxf(st1, 0.f));

        grid_barrier(sense);   // barriers #2..#1000 -> 1000 total (even): flag returns to 0
    }
}

// ---------------- phase 3: readout over stored history ----------------
// One block per t. y[t][b][o] = sum_j out[t][j][b] * eWoT[j][o] + bias. f32x2 inner.
__global__ __launch_bounds__(256) void readout_kernel(const float* __restrict__ bo,
                                                      const float* __restrict__ bv,
                                                      float* __restrict__ y) {
    __shared__ float outS[64][64];
    const int t = blockIdx.x;
    const int tid = threadIdx.x;
    const int tx = tid & 15, ty = tid >> 4;
    const int b4 = tx * 4, o4 = ty * 4;
    const float* outT = g_outAll + (size_t)t * (HID * BATCH);

    unsigned long long acc[4][2];
#pragma unroll
    for (int i = 0; i < 4; i++) { acc[i][0] = 0ull; acc[i][1] = 0ull; }
    float accv[4] = {0.f, 0.f, 0.f, 0.f};

    for (int tile = 0; tile < 16; tile++) {
        __syncthreads();
#pragma unroll
        for (int k = 0; k < 4; k++) {
            int fid = tid + k * 256;
            ((float4*)&outS[0][0])[fid] = ((const float4*)(outT + (size_t)tile * 4096))[fid];
        }
        __syncthreads();
#pragma unroll 4
        for (int jj = 0; jj < 64; jj++) {
            int j = tile * 64 + jj;
            float4 ov = *(const float4*)&outS[jj][b4];
            ulonglong2 wq = __ldg((const ulonglong2*)(g_eWoT + (size_t)j * OPAD + o4));
            unsigned long long a0 = pk2(ov.x, ov.x), a1 = pk2(ov.y, ov.y);
            unsigned long long a2 = pk2(ov.z, ov.z), a3 = pk2(ov.w, ov.w);
            acc[0][0] = ffma2(a0, wq.x, acc[0][0]); acc[0][1] = ffma2(a0, wq.y, acc[0][1]);
            acc[1][0] = ffma2(a1, wq.x, acc[1][0]); acc[1][1] = ffma2(a1, wq.y, acc[1][1]);
            acc[2][0] = ffma2(a2, wq.x, acc[2][0]); acc[2][1] = ffma2(a2, wq.y, acc[2][1]);
            acc[3][0] = ffma2(a3, wq.x, acc[3][0]); acc[3][1] = ffma2(a3, wq.y, acc[3][1]);
            if (ty == 0) {
                float w64 = __ldg(g_eWoT + (size_t)j * OPAD + 64);
                accv[0] += ov.x * w64; accv[1] += ov.y * w64;
                accv[2] += ov.z * w64; accv[3] += ov.w * w64;
            }
        }
    }

    float* yt = y + (size_t)t * (BATCH * NY);
    const float bo0 = bo[o4], bo1 = bo[o4 + 1], bo2 = bo[o4 + 2], bo3 = bo[o4 + 3];
#pragma unroll
    for (int i = 0; i < 4; i++) {
        float f0, f1, f2, f3;
        upk2(acc[i][0], f0, f1);
        upk2(acc[i][1], f2, f3);
        float* yr = yt + (size_t)(b4 + i) * NY;
        yr[o4 + 0] = f0 + bo0; yr[o4 + 1] = f1 + bo1;
        yr[o4 + 2] = f2 + bo2; yr[o4 + 3] = f3 + bo3;
        if (ty == 0) yr[64] = accv[i] + bv[0];
    }
}

// ---------------- launcher ----------------
extern "C" void kernel_launch(void* const* d_in, const int* in_sizes, int n_in,
                              void* d_out, int out_size) {
    const float* x  = (const float*)d_in[0];
    const float* Wx = (const float*)d_in[1];
    const float* Wh = (const float*)d_in[2];
    const float* bh = (const float*)d_in[3];
    const float* Wo = (const float*)d_in[4];
    const float* bo = (const float*)d_in[5];
    const float* Wv = (const float*)d_in[6];
    const float* bv = (const float*)d_in[7];
    float* y = (float*)d_out;
    (void)in_sizes; (void)n_in; (void)out_size;

    // masked effective weights
    {
        int total = HID * HID + NY * HID;
        prep_kernel<<<(total + 255) / 256, 256>>>(Wh, Wo, Wv);
    }
    // input projection for all timesteps (no sequential dependency)
    xproj_kernel<<<dim3(HID / 128, T_STEPS), 256>>>(x, Wx);
    // persistent recurrence: 128KB weights + 16KB ring + ~16KB scratch
    static const int RNN_SMEM = (32768 + 4096) * 4 + 8 * 257 * 8;  // 163904 B
    cudaFuncSetAttribute(rnn_kernel, cudaFuncAttributeMaxDynamicSharedMemorySize, RNN_SMEM);
    rnn_kernel<<<NCTA, 256, RNN_SMEM>>>(bh);
    // readout for all timesteps
    readout_kernel<<<T_STEPS, 256>>>(bo, bv, y);
}

// round 8
// speedup vs baseline: 1.2065x; 1.0038x over previous
#include <cuda_runtime.h>
#include <cuda_pipeline.h>
#include <math.h>
#include <stdint.h>

// ---------------- problem constants ----------------
#define T_STEPS 1000
#define BATCH   64
#define IN_DIM  512
#define HID     1024
#define OUT_DIM 64
#define NY      65            // O + 1 (policy + value)
#define E_SZ    819           // excitatory / nonzero readout columns
#define ALPHA   0.2f
#define OMALPHA 0.8f

// ---------------- phase-2 config ----------------
// 128 CTAs = 32 h-groups (32 h each) x 4 batch-quarters (16 b each).
#define NCTA 128
#define HPC  32               // h per CTA
#define BPC  16               // b per CTA
#define OPAD 80               // padded readout width (float4-friendly)

// ---------------- device scratch (no allocations allowed) ----------------
__device__ float g_xq[(size_t)T_STEPS * HID * BATCH];     // [t][h][b] input projection
__device__ float g_outAll[(size_t)T_STEPS * HID * BATCH]; // [t][j][b] activation history
__device__ float g_eWhP[32 * 1024 * 32];                  // [hgrp][j][hl] packed recurrent weights
__device__ float g_eWoT[HID * OPAD];                      // [j][o] readout weights (o=64 -> value head)
__device__ unsigned g_count;                              // barrier arrivals
__device__ volatile unsigned g_flag;                      // barrier sense (1000 flips/launch... even -> replay safe)

// ---------------- f32x2 packed math ----------------
__device__ __forceinline__ unsigned long long pk2(float x, float y) {
    unsigned long long r;
    asm("mov.b64 %0, {%1, %2};" : "=l"(r) : "r"(__float_as_uint(x)), "r"(__float_as_uint(y)));
    return r;
}
__device__ __forceinline__ void upk2(unsigned long long v, float &x, float &y) {
    unsigned xi, yi;
    asm("mov.b64 {%0, %1}, %2;" : "=r"(xi), "=r"(yi) : "l"(v));
    x = __uint_as_float(xi); y = __uint_as_float(yi);
}
__device__ __forceinline__ unsigned long long ffma2(unsigned long long a,
                                                    unsigned long long b,
                                                    unsigned long long c) {
    unsigned long long d;
    asm("fma.rn.f32x2 %0, %1, %2, %3;" : "=l"(d) : "l"(a), "l"(b), "l"(c));
    return d;
}

// ---------------- prep: masked effective weights ----------------
__global__ void prep_kernel(const float* __restrict__ Wh,
                            const float* __restrict__ Wo,
                            const float* __restrict__ Wv) {
    int idx = blockIdx.x * blockDim.x + threadIdx.x;
    const int N1 = HID * HID;
    if (idx < N1) {
        int h = idx >> 10, j = idx & 1023;
        float v = Wh[idx];
        v = v > 0.f ? v : 0.f;                 // relu(W)
        float s = (j < E_SZ) ? 1.f : -1.f;     // Dale sign by presynaptic column
        v = (h == j) ? 0.f : v * s;            // zero diagonal
        // pack by h-group: [hgrp][j][h&31]
        g_eWhP[(size_t)(h >> 5) * 32768 + (size_t)j * 32 + (h & 31)] = v;
    } else if (idx < N1 + NY * HID) {
        int i2 = idx - N1;
        int o = i2 >> 10, j = i2 & 1023;
        float v = (o < OUT_DIM) ? Wo[o * HID + j] : Wv[j];
        v = v > 0.f ? v : 0.f;
        if (j >= E_SZ) v = 0.f;                // masked readout columns
        g_eWoT[(size_t)j * OPAD + o] = v;
    }
}

// ---------------- phase 1: g_xq[t][h][b] = sum_k x[t][b][k]*relu(Wx[h][k]) ----------------
// Tile 64b x 128h, K-tile 16, 256 threads, per-thread 4b x 8h via f32x2.
__global__ __launch_bounds__(256) void xproj_kernel(const float* __restrict__ x,
                                                    const float* __restrict__ Wx) {
    __shared__ float As[16][64];    // [k][b]
    __shared__ float Bs[16][128];   // [k][h]
    const int t  = blockIdx.y;
    const int h0 = blockIdx.x * 128;
    const int tid = threadIdx.x;
    const int tx = tid & 15;        // b-group (4 b)
    const int ty = tid >> 4;        // h-group (8 h = 4 pairs)

    unsigned long long acc[4][4];
#pragma unroll
    for (int i = 0; i < 4; i++)
#pragma unroll
        for (int p = 0; p < 4; p++) acc[i][p] = 0ull;

    const float* xb = x + (size_t)t * BATCH * IN_DIM;
    const int bb  = tid >> 2;             // 0..63
    const int kk4 = (tid & 3) << 2;       // 0,4,8,12
    const int hh  = tid & 127;            // 0..127
    const int kq  = (tid >> 7) << 3;      // 0 or 8

    for (int k0 = 0; k0 < IN_DIM; k0 += 16) {
        __syncthreads();
        float4 av = *(const float4*)&xb[(size_t)bb * IN_DIM + k0 + kk4];
        As[kk4 + 0][bb] = av.x; As[kk4 + 1][bb] = av.y;
        As[kk4 + 2][bb] = av.z; As[kk4 + 3][bb] = av.w;
        const float* wrow = Wx + (size_t)(h0 + hh) * IN_DIM + k0 + kq;
        float4 w0 = *(const float4*)wrow;
        float4 w1 = *(const float4*)(wrow + 4);
        Bs[kq + 0][hh] = fmaxf(w0.x, 0.f); Bs[kq + 1][hh] = fmaxf(w0.y, 0.f);
        Bs[kq + 2][hh] = fmaxf(w0.z, 0.f); Bs[kq + 3][hh] = fmaxf(w0.w, 0.f);
        Bs[kq + 4][hh] = fmaxf(w1.x, 0.f); Bs[kq + 5][hh] = fmaxf(w1.y, 0.f);
        Bs[kq + 6][hh] = fmaxf(w1.z, 0.f); Bs[kq + 7][hh] = fmaxf(w1.w, 0.f);
        __syncthreads();
#pragma unroll
        for (int kk = 0; kk < 16; kk++) {
            float4 a = *(const float4*)&As[kk][tx << 2];
            ulonglong2 wA = *(const ulonglong2*)&Bs[kk][(ty << 3)];
            ulonglong2 wB = *(const ulonglong2*)&Bs[kk][(ty << 3) + 4];
            unsigned long long a0 = pk2(a.x, a.x), a1 = pk2(a.y, a.y);
            unsigned long long a2 = pk2(a.z, a.z), a3 = pk2(a.w, a.w);
            acc[0][0] = ffma2(a0, wA.x, acc[0][0]); acc[0][1] = ffma2(a0, wA.y, acc[0][1]);
            acc[0][2] = ffma2(a0, wB.x, acc[0][2]); acc[0][3] = ffma2(a0, wB.y, acc[0][3]);
            acc[1][0] = ffma2(a1, wA.x, acc[1][0]); acc[1][1] = ffma2(a1, wA.y, acc[1][1]);
            acc[1][2] = ffma2(a1, wB.x, acc[1][2]); acc[1][3] = ffma2(a1, wB.y, acc[1][3]);
            acc[2][0] = ffma2(a2, wA.x, acc[2][0]); acc[2][1] = ffma2(a2, wA.y, acc[2][1]);
            acc[2][2] = ffma2(a2, wB.x, acc[2][2]); acc[2][3] = ffma2(a2, wB.y, acc[2][3]);
            acc[3][0] = ffma2(a3, wA.x, acc[3][0]); acc[3][1] = ffma2(a3, wA.y, acc[3][1]);
            acc[3][2] = ffma2(a3, wB.x, acc[3][2]); acc[3][3] = ffma2(a3, wB.y, acc[3][3]);
        }
    }
    float* xqo = g_xq + (size_t)t * (HID * BATCH);
#pragma unroll
    for (int i = 0; i < 4; i++) {
        int b = (tx << 2) + i;
#pragma unroll
        for (int p = 0; p < 4; p++) {
            float f0, f1; upk2(acc[i][p], f0, f1);
            int h = h0 + (ty << 3) + (p << 1);
            xqo[(size_t)h * 64 + b]       = f0;
            xqo[(size_t)(h + 1) * 64 + b] = f1;
        }
    }
}

// ---------------- grid barrier (sense reversing) ----------------
__device__ __forceinline__ void grid_barrier(unsigned &sense) {
    sense ^= 1u;
    __threadfence();                 // publish this thread's global writes
    __syncthreads();
    if (threadIdx.x == 0) {
        unsigned old = atomicAdd(&g_count, 1u);
        if (old == NCTA - 1) {
            g_count = 0;
            __threadfence();
            g_flag = sense;          // release
        } else {
            while (g_flag != sense) { }
            __threadfence();         // acquire
        }
    }
    __syncthreads();
}

// ---------------- phase 2: persistent recurrent kernel ----------------
// 128 CTAs x 256 threads. CTA = (hgrp, bq): 32 h-cols x 16 b. Weights (128 KB)
// resident in shared for all 1000 steps. Warp layout: lane = bq(4) x ho(8),
// warp id = jg (8-way j-split) -> conflict-free LDS, 8 ffma2 per 2 LDS.128.
// Activation quarter-slice (64 KB/step) staged via 4-stage cp.async ring.
extern __shared__ float rnn_smem[];
__global__ __launch_bounds__(256, 1) void rnn_kernel(const float* __restrict__ bh) {
    float* sW   = rnn_smem;                         // 32768 floats (128 KB) weights [j][32h]
    float* sOut = rnn_smem + 32768;                 // 4 x 1024 floats ring (16 KB)
    unsigned long long* sRed =
        (unsigned long long*)(rnn_smem + 32768 + 4096); // 8 x 257 ull reduction scratch

    const int cta  = blockIdx.x;
    const int tid  = threadIdx.x;
    const int hgrp = cta >> 2;
    const int b0   = (cta & 3) * BPC;
    const int lane = tid & 31;
    const int bq   = lane & 3;        // 4 b's: b = b0 + bq*4 + bi
    const int ho   = lane >> 2;       // 0..7: 4 h's: h = ho*4 + {0..3}
    const int jg   = tid >> 5;        // warp id = j-group (8-way)
    const int bql  = bq * 4;
    // output-ownership mapping (one h-pair x one b per thread)
    const int hpO  = tid >> 4;        // 0..15
    const int blO  = tid & 15;
    const int hOut = hgrp * 32 + hpO * 2;
    const int bOut = b0 + blO;
    // cp.async mapping (one 16B chunk per thread per tile)
    const int cpj = tid >> 2;         // 0..63 (j within tile)
    const int cpc = (tid & 3) * 4;    // 0,4,8,12 (b chunk)

    // load this CTA's weights into shared ONCE (used for all 1000 steps)
    {
        const float4* src = (const float4*)(g_eWhP + (size_t)hgrp * 32768);
        float4* dst = (float4*)sW;
#pragma unroll
        for (int k = 0; k < 32; k++) dst[tid + k * 256] = src[tid + k * 256];
    }

    const float bh0 = bh[hOut], bh1 = bh[hOut + 1];
    float st0, st1;
    unsigned sense = 0;

    // ---- step 0: out_prev == 0 -> total = xproj + bias only ----
    {
        float xq0 = g_xq[(size_t)hOut * 64 + bOut];
        float xq1 = g_xq[(size_t)(hOut + 1) * 64 + bOut];
        st0 = ALPHA * (xq0 + bh0);
        st1 = ALPHA * (xq1 + bh1);
        g_outAll[(size_t)hOut * 64 + bOut]       = tanhf(fmaxf(st0, 0.f));
        g_outAll[(size_t)(hOut + 1) * 64 + bOut] = tanhf(fmaxf(st1, 0.f));
    }
    grid_barrier(sense);   // barrier #1 (also orders sW staging for all threads)

    // ---- steps 1..999 ----
    for (int t = 1; t < T_STEPS; t++) {
        const float* outPrev = g_outAll + (size_t)(t - 1) * (HID * BATCH);
        const float* xqt = g_xq + (size_t)t * (HID * BATCH);
        float xq0 = xqt[(size_t)hOut * 64 + bOut];
        float xq1 = xqt[(size_t)(hOut + 1) * 64 + bOut];

        // prologue: prefetch tiles 0..2 (each tile = 64 j x 16 b = 4 KB)
#pragma unroll
        for (int pti = 0; pti < 3; pti++) {
            __pipeline_memcpy_async(sOut + pti * 1024 + cpj * 16 + cpc,
                                    outPrev + (size_t)(pti * 64 + cpj) * 64 + b0 + cpc, 16);
            __pipeline_commit();
        }

        unsigned long long acc[4][2];
#pragma unroll
        for (int i = 0; i < 4; i++) { acc[i][0] = 0ull; acc[i][1] = 0ull; }

        for (int ti = 0; ti < 16; ti++) {
            __pipeline_wait_prior(2);   // this thread's chunk of tile ti arrived
            __syncthreads();            // -> whole tile arrived, prior stage consumed
            if (ti < 13) {
                int nt = ti + 3;
                __pipeline_memcpy_async(sOut + (nt & 3) * 1024 + cpj * 16 + cpc,
                                        outPrev + (size_t)(nt * 64 + cpj) * 64 + b0 + cpc, 16);
            }
            __pipeline_commit();        // commit even when empty: fixed group accounting
            const float* buf = sOut + (ti & 3) * 1024;
            const float* wb  = sW + ti * 64 * 32 + ho * 4;
#pragma unroll
            for (int i = 0; i < 8; i++) {
                int lj = jg * 8 + i;
                float4 ov = *(const float4*)(buf + lj * 16 + bql);
                ulonglong2 w = *(const ulonglong2*)(wb + lj * 32);
                unsigned long long a0 = pk2(ov.x, ov.x);
                unsigned long long a1 = pk2(ov.y, ov.y);
                unsigned long long a2 = pk2(ov.z, ov.z);
                unsigned long long a3 = pk2(ov.w, ov.w);
                acc[0][0] = ffma2(a0, w.x, acc[0][0]); acc[0][1] = ffma2(a0, w.y, acc[0][1]);
                acc[1][0] = ffma2(a1, w.x, acc[1][0]); acc[1][1] = ffma2(a1, w.y, acc[1][1]);
                acc[2][0] = ffma2(a2, w.x, acc[2][0]); acc[2][1] = ffma2(a2, w.y, acc[2][1]);
                acc[3][0] = ffma2(a3, w.x, acc[3][0]); acc[3][1] = ffma2(a3, w.y, acc[3][1]);
            }
        }

        // cross-jg reduction: 8 partials per output (h-pair, b)
#pragma unroll
        for (int bi = 0; bi < 4; bi++)
#pragma unroll
            for (int hp = 0; hp < 2; hp++)
                sRed[jg * 257 + (ho * 2 + hp) * 16 + (bql + bi)] = acc[bi][hp];
        __syncthreads();
        float r0 = 0.f, r1 = 0.f;
#pragma unroll
        for (int g = 0; g < 8; g++) {
            float f0, f1;
            upk2(sRed[g * 257 + hpO * 16 + blO], f0, f1);
            r0 += f0; r1 += f1;
        }

        st0 = OMALPHA * st0 + ALPHA * (xq0 + r0 + bh0);
        st1 = OMALPHA * st1 + ALPHA * (xq1 + r1 + bh1);
        float* outCur = g_outAll + (size_t)t * (HID * BATCH);
        outCur[(size_t)hOut * 64 + bOut]       = tanhf(fmaxf(st0, 0.f));
        outCur[(size_t)(hOut + 1) * 64 + bOut] = tanhf(fmaxf(st1, 0.f));

        grid_barrier(sense);   // barriers #2..#1000 -> 1000 total (even): flag returns to 0
    }
}

// ---------------- phase 3: readout over stored history ----------------
// One block per t. y[t][b][o] = sum_j out[t][j][b] * eWoT[j][o] + bias. f32x2 inner.
__global__ __launch_bounds__(256) void readout_kernel(const float* __restrict__ bo,
                                                      const float* __restrict__ bv,
                                                      float* __restrict__ y) {
    __shared__ float outS[64][64];
    const int t = blockIdx.x;
    const int tid = threadIdx.x;
    const int tx = tid & 15, ty = tid >> 4;
    const int b4 = tx * 4, o4 = ty * 4;
    const float* outT = g_outAll + (size_t)t * (HID * BATCH);

    unsigned long long acc[4][2];
#pragma unroll
    for (int i = 0; i < 4; i++) { acc[i][0] = 0ull; acc[i][1] = 0ull; }
    float accv[4] = {0.f, 0.f, 0.f, 0.f};

    for (int tile = 0; tile < 16; tile++) {
        __syncthreads();
#pragma unroll
        for (int k = 0; k < 4; k++) {
            int fid = tid + k * 256;
            ((float4*)&outS[0][0])[fid] = ((const float4*)(outT + (size_t)tile * 4096))[fid];
        }
        __syncthreads();
#pragma unroll 4
        for (int jj = 0; jj < 64; jj++) {
            int j = tile * 64 + jj;
            float4 ov = *(const float4*)&outS[jj][b4];
            ulonglong2 wq = __ldg((const ulonglong2*)(g_eWoT + (size_t)j * OPAD + o4));
            unsigned long long a0 = pk2(ov.x, ov.x), a1 = pk2(ov.y, ov.y);
            unsigned long long a2 = pk2(ov.z, ov.z), a3 = pk2(ov.w, ov.w);
            acc[0][0] = ffma2(a0, wq.x, acc[0][0]); acc[0][1] = ffma2(a0, wq.y, acc[0][1]);
            acc[1][0] = ffma2(a1, wq.x, acc[1][0]); acc[1][1] = ffma2(a1, wq.y, acc[1][1]);
            acc[2][0] = ffma2(a2, wq.x, acc[2][0]); acc[2][1] = ffma2(a2, wq.y, acc[2][1]);
            acc[3][0] = ffma2(a3, wq.x, acc[3][0]); acc[3][1] = ffma2(a3, wq.y, acc[3][1]);
            if (ty == 0) {
                float w64 = __ldg(g_eWoT + (size_t)j * OPAD + 64);
                accv[0] += ov.x * w64; accv[1] += ov.y * w64;
                accv[2] += ov.z * w64; accv[3] += ov.w * w64;
            }
        }
    }

    float* yt = y + (size_t)t * (BATCH * NY);
    const float bo0 = bo[o4], bo1 = bo[o4 + 1], bo2 = bo[o4 + 2], bo3 = bo[o4 + 3];
#pragma unroll
    for (int i = 0; i < 4; i++) {
        float f0, f1, f2, f3;
        upk2(acc[i][0], f0, f1);
        upk2(acc[i][1], f2, f3);
        float* yr = yt + (size_t)(b4 + i) * NY;
        yr[o4 + 0] = f0 + bo0; yr[o4 + 1] = f1 + bo1;
        yr[o4 + 2] = f2 + bo2; yr[o4 + 3] = f3 + bo3;
        if (ty == 0) yr[64] = accv[i] + bv[0];
    }
}

// ---------------- launcher ----------------
extern "C" void kernel_launch(void* const* d_in, const int* in_sizes, int n_in,
                              void* d_out, int out_size) {
    const float* x  = (const float*)d_in[0];
    const float* Wx = (const float*)d_in[1];
    const float* Wh = (const float*)d_in[2];
    const float* bh = (const float*)d_in[3];
    const float* Wo = (const float*)d_in[4];
    const float* bo = (const float*)d_in[5];
    const float* Wv = (const float*)d_in[6];
    const float* bv = (const float*)d_in[7];
    float* y = (float*)d_out;
    (void)in_sizes; (void)n_in; (void)out_size;

    // masked effective weights
    {
        int total = HID * HID + NY * HID;
        prep_kernel<<<(total + 255) / 256, 256>>>(Wh, Wo, Wv);
    }
    // input projection for all timesteps (no sequential dependency)
    xproj_kernel<<<dim3(HID / 128, T_STEPS), 256>>>(x, Wx);
    // persistent recurrence: 128KB weights + 16KB ring + ~16KB scratch
    static const int RNN_SMEM = (32768 + 4096) * 4 + 8 * 257 * 8;  // 163904 B
    cudaFuncSetAttribute(rnn_kernel, cudaFuncAttributeMaxDynamicSharedMemorySize, RNN_SMEM);
    rnn_kernel<<<NCTA, 256, RNN_SMEM>>>(bh);
    // readout for all timesteps
    readout_kernel<<<T_STEPS, 256>>>(bo, bv, y);
}